// round 14
// baseline (speedup 1.0000x reference)
#include <cuda_runtime.h>
#include <cuda_fp16.h>
#include <cstdint>

// Problem constants
#define Bb  2
#define Ss  2048
#define Dd  1024
#define Hh  16
#define HDd 64
#define MS  (Bb*Ss)          // 4096 rows
#define LN_EPS 1e-5f
#define GK 1024
#define PSZ ((size_t)MS * Dd)
#define WSZ ((size_t)Dd * Dd)

// ---------------------------------------------------------------------------
// Scratch (device globals)
// ---------------------------------------------------------------------------
__device__ float g_tmp[MS*Dd];                 // pre-LN
__device__ __half g_xh[3*MS*Dd];               // staged inputs (q,k,v planes)
__device__ __half g_wth[4*Dd*Dd];              // W^T [N][K] fp16 (wq,wk,wv,wo)
__device__ __half g_ph[3*MS*Dd];               // projections (Q,K,V planes)
__device__ __half g_oh[MS*Dd];                 // attention out (fp16)

// ---------------------------------------------------------------------------
// Helpers
// ---------------------------------------------------------------------------
__device__ __forceinline__ uint32_t smem_u32(const void* p) {
    uint32_t a;
    asm("{ .reg .u64 t; cvta.to.shared.u64 t, %1; cvt.u32.u64 %0, t; }"
        : "=r"(a) : "l"(p));
    return a;
}
__device__ __forceinline__ void cpa16(uint32_t s, const void* g) {
    asm volatile("cp.async.cg.shared.global [%0], [%1], 16;" :: "r"(s), "l"(g));
}
#define CPA_COMMIT() asm volatile("cp.async.commit_group;" ::: "memory")
#define CPA_WAIT0()  asm volatile("cp.async.wait_group 0;" ::: "memory")
#define CPA_WAIT1()  asm volatile("cp.async.wait_group 1;" ::: "memory")

__device__ __forceinline__ void ldm4(uint32_t a, uint32_t r[4]) {
    asm volatile("ldmatrix.sync.aligned.m8n8.x4.shared.b16 {%0,%1,%2,%3}, [%4];"
                 : "=r"(r[0]), "=r"(r[1]), "=r"(r[2]), "=r"(r[3]) : "r"(a));
}
__device__ __forceinline__ void ldm4t(uint32_t a, uint32_t r[4]) {
    asm volatile("ldmatrix.sync.aligned.m8n8.x4.trans.shared.b16 {%0,%1,%2,%3}, [%4];"
                 : "=r"(r[0]), "=r"(r[1]), "=r"(r[2]), "=r"(r[3]) : "r"(a));
}
// fp16 HMMA, fp32 accumulate
__device__ __forceinline__ void mma16816(float d[4], const uint32_t a[4],
                                         uint32_t b0, uint32_t b1) {
    asm volatile(
        "mma.sync.aligned.m16n8k16.row.col.f32.f16.f16.f32 "
        "{%0,%1,%2,%3}, {%4,%5,%6,%7}, {%8,%9}, {%0,%1,%2,%3};"
        : "+f"(d[0]), "+f"(d[1]), "+f"(d[2]), "+f"(d[3])
        : "r"(a[0]), "r"(a[1]), "r"(a[2]), "r"(a[3]), "r"(b0), "r"(b1));
}
__device__ __forceinline__ uint32_t pack_h2(float x, float y) {
    __half hx = __float2half_rn(x), hy = __float2half_rn(y);
    return (uint32_t)__half_as_ushort(hx) | ((uint32_t)__half_as_ushort(hy) << 16);
}

// ---------------------------------------------------------------------------
// fp16 single-product HMMA GEMM: C = A @ Wh (+resid)
// 256 threads, CTA tile 128x256, 8 warps of 64x64 (2m x 4n grid).
// SMEM/stage: A @0 (10240B, 128 rows x pitch-40), B @10240 (20480B, 256 rows).
// Stage stride 30720; 2 stages = 61440 B. ~190 regs -> 1 CTA/SM.
// grid.z batches independent (A,W,OH) planes via PSZ/WSZ strides.
// ---------------------------------------------------------------------------
#define GEMM_SMEM 61440

__global__ __launch_bounds__(256)
void gemm_tc(const __half* __restrict__ Ah,
             const __half* __restrict__ Wh,
             const float* __restrict__ resid, float* __restrict__ C,
             __half* __restrict__ OH)
{
    extern __shared__ __half S[];
    const int tid  = threadIdx.x;
    const int lane = tid & 31;
    const int wid  = tid >> 5;            // 0..7
    const int z    = blockIdx.z;
    const int bm = blockIdx.y * 128;
    const int bn = blockIdx.x * 256;
    const int wm = (wid & 1) * 64;        // 2 warp rows
    const int wn = (wid >> 1) * 64;       // 4 warp cols (64 wide)

    const size_t zo = (size_t)z * PSZ;
    const __half* gA = Ah + zo + (size_t)bm * GK;
    const __half* gB = Wh + (size_t)z * WSZ + (size_t)bn * GK;

    const uint32_t sbase = smem_u32(S);

    float d[4][8][4];
    #pragma unroll
    for (int i = 0; i < 4; i++)
        #pragma unroll
        for (int j = 0; j < 8; j++)
            #pragma unroll
            for (int e = 0; e < 4; e++) d[i][j][e] = 0.f;

    const uint32_t acb_row = (uint32_t)(lane & 15);
    const uint32_t acb_col = (uint32_t)((lane >> 4) * 8);

    // prologue: stage 0, k0 = 0. A: 512 uint4 (2 its); B: 1024 uint4 (4 its).
    {
        #pragma unroll
        for (int it = 0; it < 2; it++) {
            int f = tid + it * 256;
            int r = f >> 2;
            int u = f & 3;
            cpa16(sbase + (uint32_t)(r * 40 + u * 8) * 2,
                  gA + (size_t)r * GK + u * 8);
        }
        #pragma unroll
        for (int it = 0; it < 4; it++) {
            int f = tid + it * 256;
            int r = f >> 2;
            int u = f & 3;
            cpa16(sbase + 10240u + (uint32_t)(r * 40 + u * 8) * 2,
                  gB + (size_t)r * GK + u * 8);
        }
        CPA_COMMIT();
        CPA_WAIT0();
        __syncthreads();
    }

    for (int ic = 0; ic < 32; ic++) {
        const int st = ic & 1;
        if (ic + 1 < 32) {
            const int k0 = (ic + 1) * 32;
            const uint32_t sb2 = sbase + (uint32_t)((st ^ 1) * 30720);
            #pragma unroll
            for (int it = 0; it < 2; it++) {
                int f = tid + it * 256;
                int r = f >> 2;
                int u = f & 3;
                cpa16(sb2 + (uint32_t)(r * 40 + u * 8) * 2,
                      gA + (size_t)r * GK + k0 + u * 8);
            }
            #pragma unroll
            for (int it = 0; it < 4; it++) {
                int f = tid + it * 256;
                int r = f >> 2;
                int u = f & 3;
                cpa16(sb2 + 10240u + (uint32_t)(r * 40 + u * 8) * 2,
                      gB + (size_t)r * GK + k0 + u * 8);
            }
        }
        CPA_COMMIT();

        const uint32_t sb = sbase + (uint32_t)(st * 30720);
        #pragma unroll
        for (int ks = 0; ks < 2; ks++) {
            const uint32_t cb = (uint32_t)(ks * 16) * 2 + acb_col * 2;

            uint32_t ah[4][4], bh[4][4];
            #pragma unroll
            for (int i = 0; i < 4; i++)
                ldm4(sb + (uint32_t)((wm + i * 16) + acb_row) * 80u + cb, ah[i]);
            #pragma unroll
            for (int nb = 0; nb < 4; nb++)
                ldm4(sb + 10240u + (uint32_t)((wn + nb * 16) + acb_row) * 80u + cb, bh[nb]);

            #pragma unroll
            for (int i = 0; i < 4; i++)
                #pragma unroll
                for (int nb = 0; nb < 4; nb++) {
                    mma16816(d[i][2*nb],     ah[i], bh[nb][0], bh[nb][2]);
                    mma16816(d[i][2*nb + 1], ah[i], bh[nb][1], bh[nb][3]);
                }
        }
        CPA_WAIT0();
        __syncthreads();
    }

    const int er = bm + wm + (lane >> 2);
    const int ec = bn + wn + (lane & 3) * 2;
    #pragma unroll
    for (int i = 0; i < 4; i++) {
        const int r1 = er + i * 16;
        #pragma unroll
        for (int jj = 0; jj < 8; jj++) {
            const int c = ec + jj * 8;
            size_t o0 = (size_t)r1 * GK + c;
            size_t o1 = (size_t)(r1 + 8) * GK + c;
            if (OH) {
                *(uint32_t*)(OH + zo + o0) = pack_h2(d[i][jj][0], d[i][jj][1]);
                *(uint32_t*)(OH + zo + o1) = pack_h2(d[i][jj][2], d[i][jj][3]);
            } else {
                float2 v0 = make_float2(d[i][jj][0], d[i][jj][1]);
                float2 v1 = make_float2(d[i][jj][2], d[i][jj][3]);
                if (resid) {
                    float2 q0 = *(const float2*)(resid + o0);
                    float2 q1 = *(const float2*)(resid + o1);
                    v0.x += q0.x; v0.y += q0.y;
                    v1.x += q1.x; v1.y += q1.y;
                }
                *(float2*)(C + o0) = v0;
                *(float2*)(C + o1) = v1;
            }
        }
    }
}

// ---------------------------------------------------------------------------
// fp32 -> fp16; grid.z selects source (q,k,v) -> plane z
// ---------------------------------------------------------------------------
__global__ __launch_bounds__(256) void conv_act_all(
    const float* __restrict__ X0, const float* __restrict__ X1,
    const float* __restrict__ X2, __half* __restrict__ H)
{
    const int z = blockIdx.z;
    const float* X = (z == 0) ? X0 : (z == 1) ? X1 : X2;
    size_t i = (size_t)blockIdx.x * 256 + threadIdx.x;
    float4 v = ((const float4*)X)[i];
    __half h[4];
    h[0] = __float2half_rn(v.x);
    h[1] = __float2half_rn(v.y);
    h[2] = __float2half_rn(v.z);
    h[3] = __float2half_rn(v.w);
    uint64_t hp;
    memcpy(&hp, h, 8);
    ((uint64_t*)H)[(size_t)z * (PSZ / 4) + i] = hp;
}

// ---------------------------------------------------------------------------
// W [K][N] fp32 -> W^T fp16 [N][K]; grid.z selects (wq,wk,wv,wo)
// ---------------------------------------------------------------------------
__global__ __launch_bounds__(256) void conv_wt_all(
    const float* __restrict__ W0, const float* __restrict__ W1,
    const float* __restrict__ W2, const float* __restrict__ W3,
    __half* __restrict__ TH)
{
    __shared__ float t[32][33];
    const int z = blockIdx.z;
    const float* W = (z == 0) ? W0 : (z == 1) ? W1 : (z == 2) ? W2 : W3;
    const size_t zw = (size_t)z * WSZ;
    const int bxn = blockIdx.x * 32;
    const int byk = blockIdx.y * 32;
    const int tx = threadIdx.x & 31;
    const int ty4 = (threadIdx.x >> 5) * 4;

    #pragma unroll
    for (int j = 0; j < 4; j++)
        t[ty4 + j][tx] = W[(size_t)(byk + ty4 + j) * Dd + bxn + tx];
    __syncthreads();

    #pragma unroll
    for (int j = 0; j < 4; j++)
        TH[zw + (size_t)(bxn + ty4 + j) * Dd + byk + tx] =
            __float2half_rn(t[tx][ty4 + j]);
}

// ---------------------------------------------------------------------------
// fp16 HMMA flash attention (causal), single-product S and O.
// Q persistent in SMEM; K/V double-buffer. Heavy CTAs scheduled first
// (bx reversed) to reduce the load-imbalance tail.
// ---------------------------------------------------------------------------
#define AT_ROWB    144
#define AT_TILE_B  (64 * AT_ROWB)          // 9216
#define AT_KVSTG_B (2 * AT_TILE_B)         // 18432: Kh + Vh
#define AT_Q_B     18432
#define ATTN2_SMEM (AT_Q_B + 2 * AT_KVSTG_B)   // 55296
#define CS 0.18033688011112042f            // log2(e)/8

__global__ __launch_bounds__(256, 2) void attn_tc(
    const __half* __restrict__ Qh,
    const __half* __restrict__ Kh, const __half* __restrict__ Vh,
    __half* __restrict__ Oh)
{
    extern __shared__ char smc[];
    const int tid = threadIdx.x;
    const int lane = tid & 31;
    const int w = tid >> 5;
    const int bx = (int)gridDim.x - 1 - (int)blockIdx.x;   // heavy first
    const int h = blockIdx.y, b = blockIdx.z;
    const int q0 = bx * 128;
    const uint32_t sb = smem_u32(smc);
    const uint32_t kvb = sb + AT_Q_B;
    const size_t headoff = (size_t)b * Ss * Dd + (size_t)h * HDd;

    // ---- Q tile -> persistent SMEM
    {
        const __half* gq = Qh + headoff + (size_t)q0 * Dd;
        #pragma unroll
        for (int it = 0; it < 4; it++) {
            int f = tid + it * 256;
            int r = f >> 3, ch = f & 7;
            uint32_t so = sb + (uint32_t)(r * AT_ROWB + ch * 16);
            cpa16(so, gq + (size_t)r * Dd + ch * 8);
        }
        CPA_COMMIT();
        CPA_WAIT0();
    }
    __syncthreads();

    const uint32_t qlb = sb + (uint32_t)((16 * w + (lane & 15)) * AT_ROWB
                                         + (lane >> 4) * 16);

    float oacc[8][4];
    #pragma unroll
    for (int i = 0; i < 8; i++)
        #pragma unroll
        for (int e = 0; e < 4; e++) oacc[i][e] = 0.f;
    float m0 = -1e30f, m1 = -1e30f, l0 = 0.f, l1 = 0.f;
    const int r0g = q0 + 16 * w + (lane >> 2);
    const int r1g = r0g + 8;

    const int nkt = 2 * bx + 2;
    const __half *gkh = Kh + headoff, *gvh = Vh + headoff;

    // prologue: KV tile 0 -> stage 0
    #pragma unroll
    for (int it = 0; it < 2; it++) {
        int f = tid + it * 256;
        int r = f >> 3, ch = f & 7;
        uint32_t so = kvb + (uint32_t)(r * AT_ROWB + ch * 16);
        size_t go = (size_t)r * Dd + ch * 8;
        cpa16(so,             gkh + go);
        cpa16(so + AT_TILE_B, gvh + go);
    }
    CPA_COMMIT();

    for (int kt = 0; kt < nkt; kt++) {
        __syncthreads();
        if (kt + 1 < nkt) {
            const uint32_t st2 = kvb + (uint32_t)(((kt + 1) & 1) * AT_KVSTG_B);
            const size_t kb = (size_t)(kt + 1) * 64 * Dd;
            #pragma unroll
            for (int it = 0; it < 2; it++) {
                int f = tid + it * 256;
                int r = f >> 3, ch = f & 7;
                uint32_t so = st2 + (uint32_t)(r * AT_ROWB + ch * 16);
                size_t go = kb + (size_t)r * Dd + ch * 8;
                cpa16(so,             gkh + go);
                cpa16(so + AT_TILE_B, gvh + go);
            }
            CPA_COMMIT();
            CPA_WAIT1();
        } else {
            CPA_WAIT0();
        }
        __syncthreads();

        const int k0 = kt * 64;
        const bool active = (k0 <= q0 + 16 * w + 15);   // warp-uniform
        if (active) {
            const uint32_t stg = kvb + (uint32_t)((kt & 1) * AT_KVSTG_B);
            float sacc[8][4];
            #pragma unroll
            for (int i = 0; i < 8; i++)
                #pragma unroll
                for (int e = 0; e < 4; e++) sacc[i][e] = 0.f;

            const uint32_t lb = stg + (uint32_t)((lane & 15) * AT_ROWB
                                                 + (lane >> 4) * 16);
            #pragma unroll
            for (int c = 0; c < 4; c++) {
                uint32_t qh4[4];
                ldm4(qlb + (uint32_t)(c * 32), qh4);
                #pragma unroll
                for (int g = 0; g < 4; g++) {
                    uint32_t kh4[4];
                    ldm4(lb + (uint32_t)(g * 16 * AT_ROWB + c * 32), kh4);
                    mma16816(sacc[2*g],   qh4, kh4[0], kh4[2]);
                    mma16816(sacc[2*g+1], qh4, kh4[1], kh4[3]);
                }
            }

            if (k0 + 63 > q0 + 16 * w) {
                #pragma unroll
                for (int nb = 0; nb < 8; nb++) {
                    int col = k0 + nb * 8 + (lane & 3) * 2;
                    if (col     > r0g) sacc[nb][0] = -1e30f;
                    if (col + 1 > r0g) sacc[nb][1] = -1e30f;
                    if (col     > r1g) sacc[nb][2] = -1e30f;
                    if (col + 1 > r1g) sacc[nb][3] = -1e30f;
                }
            }

            float mx0 = -1e30f, mx1 = -1e30f;
            #pragma unroll
            for (int nb = 0; nb < 8; nb++) {
                mx0 = fmaxf(mx0, fmaxf(sacc[nb][0], sacc[nb][1]));
                mx1 = fmaxf(mx1, fmaxf(sacc[nb][2], sacc[nb][3]));
            }
            mx0 = fmaxf(mx0, __shfl_xor_sync(0xffffffffu, mx0, 1));
            mx0 = fmaxf(mx0, __shfl_xor_sync(0xffffffffu, mx0, 2));
            mx1 = fmaxf(mx1, __shfl_xor_sync(0xffffffffu, mx1, 1));
            mx1 = fmaxf(mx1, __shfl_xor_sync(0xffffffffu, mx1, 2));
            const float nm0 = fmaxf(m0, mx0), nm1 = fmaxf(m1, mx1);
            const float a0 = exp2f((m0 - nm0) * CS);
            const float a1 = exp2f((m1 - nm1) * CS);
            m0 = nm0; m1 = nm1;
            const float c0 = nm0 * CS, c1 = nm1 * CS;
            float s0 = 0.f, s1 = 0.f;
            #pragma unroll
            for (int nb = 0; nb < 8; nb++) {
                float p0 = exp2f(fmaf(sacc[nb][0], CS, -c0));
                float p1 = exp2f(fmaf(sacc[nb][1], CS, -c0));
                float p2 = exp2f(fmaf(sacc[nb][2], CS, -c1));
                float p3 = exp2f(fmaf(sacc[nb][3], CS, -c1));
                sacc[nb][0] = p0; sacc[nb][1] = p1;
                sacc[nb][2] = p2; sacc[nb][3] = p3;
                s0 += p0 + p1;
                s1 += p2 + p3;
            }
            s0 += __shfl_xor_sync(0xffffffffu, s0, 1);
            s0 += __shfl_xor_sync(0xffffffffu, s0, 2);
            s1 += __shfl_xor_sync(0xffffffffu, s1, 1);
            s1 += __shfl_xor_sync(0xffffffffu, s1, 2);
            l0 = l0 * a0 + s0;
            l1 = l1 * a1 + s1;
            #pragma unroll
            for (int i = 0; i < 8; i++) {
                oacc[i][0] *= a0; oacc[i][1] *= a0;
                oacc[i][2] *= a1; oacc[i][3] *= a1;
            }

            // O += Ph · Vh
            #pragma unroll
            for (int j = 0; j < 4; j++) {
                uint32_t pa[4];
                pa[0] = pack_h2(sacc[2*j][0],   sacc[2*j][1]);
                pa[1] = pack_h2(sacc[2*j][2],   sacc[2*j][3]);
                pa[2] = pack_h2(sacc[2*j+1][0], sacc[2*j+1][1]);
                pa[3] = pack_h2(sacc[2*j+1][2], sacc[2*j+1][3]);
                const uint32_t vb = stg + AT_TILE_B
                    + (uint32_t)((16 * j + (lane & 15)) * AT_ROWB + (lane >> 4) * 16);
                #pragma unroll
                for (int dp = 0; dp < 4; dp++) {
                    uint32_t vh4[4];
                    ldm4t(vb + (uint32_t)(dp * 32), vh4);
                    mma16816(oacc[2*dp],   pa, vh4[0], vh4[1]);
                    mma16816(oacc[2*dp+1], pa, vh4[2], vh4[3]);
                }
            }
        }
    }

    const float i0 = 1.f / l0, i1 = 1.f / l1;
    const size_t ro0 = (size_t)b * Ss * Dd + (size_t)r0g * Dd + (size_t)h * HDd;
    const size_t ro1 = ro0 + 8 * Dd;
    #pragma unroll
    for (int nb = 0; nb < 8; nb++) {
        const int dcol = nb * 8 + (lane & 3) * 2;
        *(uint32_t*)(Oh + ro0 + dcol) = pack_h2(oacc[nb][0] * i0, oacc[nb][1] * i0);
        *(uint32_t*)(Oh + ro1 + dcol) = pack_h2(oacc[nb][2] * i1, oacc[nb][3] * i1);
    }
}

// ---------------------------------------------------------------------------
// LayerNorm over last dim (1024)
// ---------------------------------------------------------------------------
__global__ __launch_bounds__(256) void ln_kernel(
    const float* __restrict__ X, const float* __restrict__ gamma,
    const float* __restrict__ beta, float* __restrict__ Y)
{
    const int row = blockIdx.x;
    const int t = threadIdx.x;
    const float4 v = ((const float4*)(X + (size_t)row * Dd))[t];

    float s  = v.x + v.y + v.z + v.w;
    float ss = v.x * v.x + v.y * v.y + v.z * v.z + v.w * v.w;
    #pragma unroll
    for (int o = 16; o > 0; o >>= 1) {
        s  += __shfl_xor_sync(0xffffffffu, s,  o);
        ss += __shfl_xor_sync(0xffffffffu, ss, o);
    }
    __shared__ float sh[8][2];
    if ((t & 31) == 0) { sh[t >> 5][0] = s; sh[t >> 5][1] = ss; }
    __syncthreads();
    float ts = 0.f, tss = 0.f;
    #pragma unroll
    for (int i = 0; i < 8; i++) { ts += sh[i][0]; tss += sh[i][1]; }

    const float mu  = ts * (1.0f / Dd);
    const float var = tss * (1.0f / Dd) - mu * mu;
    const float inv = rsqrtf(var + LN_EPS);

    const float4 gg = ((const float4*)gamma)[t];
    const float4 bb = ((const float4*)beta)[t];
    float4 y;
    y.x = (v.x - mu) * inv * gg.x + bb.x;
    y.y = (v.y - mu) * inv * gg.y + bb.y;
    y.z = (v.z - mu) * inv * gg.z + bb.z;
    y.w = (v.w - mu) * inv * gg.w + bb.w;
    ((float4*)(Y + (size_t)row * Dd))[t] = y;
}

// ---------------------------------------------------------------------------
// Launch. Inputs: q, k, v, wq, wk, wv, wo, gamma, beta, mask (causal; unused).
// ---------------------------------------------------------------------------
extern "C" void kernel_launch(void* const* d_in, const int* in_sizes, int n_in,
                              void* d_out, int out_size)
{
    const float* q     = (const float*)d_in[0];
    const float* k     = (const float*)d_in[1];
    const float* v     = (const float*)d_in[2];
    const float* wq    = (const float*)d_in[3];
    const float* wk    = (const float*)d_in[4];
    const float* wv    = (const float*)d_in[5];
    const float* wo    = (const float*)d_in[6];
    const float* gamma = (const float*)d_in[7];
    const float* beta  = (const float*)d_in[8];
    float* out = (float*)d_out;

    float* gtmp;
    __half *gxh, *gwth, *gph, *goh;
    cudaGetSymbolAddress((void**)&gtmp, g_tmp);
    cudaGetSymbolAddress((void**)&gxh,  g_xh);
    cudaGetSymbolAddress((void**)&gwth, g_wth);
    cudaGetSymbolAddress((void**)&gph,  g_ph);
    cudaGetSymbolAddress((void**)&goh,  g_oh);

    cudaFuncSetAttribute(gemm_tc,
                         cudaFuncAttributeMaxDynamicSharedMemorySize, GEMM_SMEM);
    cudaFuncSetAttribute(attn_tc,
                         cudaFuncAttributeMaxDynamicSharedMemorySize, ATTN2_SMEM);

    const dim3 blk256(256);

    // conversions up front (2 launches)
    conv_wt_all<<<dim3(Dd / 32, Dd / 32, 4), blk256>>>(wq, wk, wv, wo, gwth);
    conv_act_all<<<dim3(MS * Dd / 4 / 256, 1, 3), blk256>>>(q, k, v, gxh);

    // Q/K/V projections: one batched launch (grid.z = 3), 128x256 CTA tiles
    gemm_tc<<<dim3(Dd / 256, MS / 128, 3), blk256, GEMM_SMEM>>>(
        gxh, gwth, nullptr, nullptr, gph);

    // flash attention: single-product S and O (heavy CTAs first)
    attn_tc<<<dim3(Ss / 128, Hh, Bb), blk256, ATTN2_SMEM>>>(
        gph, gph + PSZ, gph + 2 * PSZ, goh);

    // output projection + residual (fp32 out); z=0, W plane via pointer offset
    gemm_tc<<<dim3(Dd / 256, MS / 128, 1), blk256, GEMM_SMEM>>>(
        goh, gwth + 3 * WSZ, q, gtmp, nullptr);

    // LayerNorm
    ln_kernel<<<MS, blk256>>>(gtmp, gamma, beta, out);
}

// round 15
// speedup vs baseline: 1.0580x; 1.0580x over previous
#include <cuda_runtime.h>
#include <cuda_fp16.h>
#include <cstdint>

// Problem constants
#define Bb  2
#define Ss  2048
#define Dd  1024
#define Hh  16
#define HDd 64
#define MS  (Bb*Ss)          // 4096 rows
#define LN_EPS 1e-5f
#define GK 1024
#define PSZ ((size_t)MS * Dd)
#define WSZ ((size_t)Dd * Dd)

// ---------------------------------------------------------------------------
// Scratch (device globals)
// ---------------------------------------------------------------------------
__device__ float g_tmp[MS*Dd];                 // pre-LN
__device__ __half g_xh[3*MS*Dd];               // staged inputs (q,k,v planes)
__device__ __half g_wth[4*Dd*Dd];              // W^T [N][K] fp16 (wq,wk,wv,wo)
__device__ __half g_ph[3*MS*Dd];               // projections (Q,K,V planes)
__device__ __half g_oh[MS*Dd];                 // attention out (fp16)

// ---------------------------------------------------------------------------
// Helpers
// ---------------------------------------------------------------------------
__device__ __forceinline__ uint32_t smem_u32(const void* p) {
    uint32_t a;
    asm("{ .reg .u64 t; cvta.to.shared.u64 t, %1; cvt.u32.u64 %0, t; }"
        : "=r"(a) : "l"(p));
    return a;
}
__device__ __forceinline__ void cpa16(uint32_t s, const void* g) {
    asm volatile("cp.async.cg.shared.global [%0], [%1], 16;" :: "r"(s), "l"(g));
}
#define CPA_COMMIT() asm volatile("cp.async.commit_group;" ::: "memory")
#define CPA_WAIT0()  asm volatile("cp.async.wait_group 0;" ::: "memory")
#define CPA_WAIT1()  asm volatile("cp.async.wait_group 1;" ::: "memory")

__device__ __forceinline__ void ldm4(uint32_t a, uint32_t r[4]) {
    asm volatile("ldmatrix.sync.aligned.m8n8.x4.shared.b16 {%0,%1,%2,%3}, [%4];"
                 : "=r"(r[0]), "=r"(r[1]), "=r"(r[2]), "=r"(r[3]) : "r"(a));
}
__device__ __forceinline__ void ldm4t(uint32_t a, uint32_t r[4]) {
    asm volatile("ldmatrix.sync.aligned.m8n8.x4.trans.shared.b16 {%0,%1,%2,%3}, [%4];"
                 : "=r"(r[0]), "=r"(r[1]), "=r"(r[2]), "=r"(r[3]) : "r"(a));
}
// fp16 HMMA, fp32 accumulate
__device__ __forceinline__ void mma16816(float d[4], const uint32_t a[4],
                                         uint32_t b0, uint32_t b1) {
    asm volatile(
        "mma.sync.aligned.m16n8k16.row.col.f32.f16.f16.f32 "
        "{%0,%1,%2,%3}, {%4,%5,%6,%7}, {%8,%9}, {%0,%1,%2,%3};"
        : "+f"(d[0]), "+f"(d[1]), "+f"(d[2]), "+f"(d[3])
        : "r"(a[0]), "r"(a[1]), "r"(a[2]), "r"(a[3]), "r"(b0), "r"(b1));
}
__device__ __forceinline__ uint32_t pack_h2(float x, float y) {
    __half hx = __float2half_rn(x), hy = __float2half_rn(y);
    return (uint32_t)__half_as_ushort(hx) | ((uint32_t)__half_as_ushort(hy) << 16);
}

// ---------------------------------------------------------------------------
// fp16 single-product HMMA GEMM: C = A @ Wh (+resid)  [R13 frozen]
// 256 threads, 128x128 CTA tile, 64x32 warp tile, 2 CTAs/SM.
// ---------------------------------------------------------------------------
#define GEMM_SMEM 40960

__global__ __launch_bounds__(256, 2)
void gemm_tc(const __half* __restrict__ Ah,
             const __half* __restrict__ Wh,
             const float* __restrict__ resid, float* __restrict__ C,
             __half* __restrict__ OH)
{
    extern __shared__ __half S[];
    const int tid  = threadIdx.x;
    const int lane = tid & 31;
    const int wid  = tid >> 5;            // 0..7
    const int bm = blockIdx.y * 128;
    const int bn = blockIdx.x * 128;
    const int wm = (wid & 1) * 64;
    const int wn = (wid >> 1) * 32;

    const __half* gA = Ah + (size_t)bm * GK;
    const __half* gB = Wh + (size_t)bn * GK;

    const uint32_t sbase = smem_u32(S);

    float d[4][4][4];
    #pragma unroll
    for (int i = 0; i < 4; i++)
        #pragma unroll
        for (int j = 0; j < 4; j++)
            #pragma unroll
            for (int e = 0; e < 4; e++) d[i][j][e] = 0.f;

    const uint32_t acb_row = (uint32_t)(lane & 15);
    const uint32_t acb_col = (uint32_t)((lane >> 4) * 8);

    {
        #pragma unroll
        for (int it = 0; it < 2; it++) {
            int f = tid + it * 256;
            int r = f >> 2;
            int u = f & 3;
            uint32_t so = sbase + (uint32_t)(r * 40 + u * 8) * 2;
            size_t go = (size_t)r * GK + u * 8;
            cpa16(so,          gA + go);
            cpa16(so + 10240u, gB + go);
        }
        CPA_COMMIT();
        CPA_WAIT0();
        __syncthreads();
    }

    for (int ic = 0; ic < 32; ic++) {
        const int st = ic & 1;
        if (ic + 1 < 32) {
            const int k0 = (ic + 1) * 32;
            const uint32_t sb2 = sbase + (uint32_t)((st ^ 1) * 20480);
            #pragma unroll
            for (int it = 0; it < 2; it++) {
                int f = tid + it * 256;
                int r = f >> 2;
                int u = f & 3;
                uint32_t so = sb2 + (uint32_t)(r * 40 + u * 8) * 2;
                size_t go = (size_t)r * GK + k0 + u * 8;
                cpa16(so,          gA + go);
                cpa16(so + 10240u, gB + go);
            }
        }
        CPA_COMMIT();

        const uint32_t sb = sbase + (uint32_t)(st * 20480);
        #pragma unroll
        for (int ks = 0; ks < 2; ks++) {
            const uint32_t cb = (uint32_t)(ks * 16) * 2 + acb_col * 2;

            uint32_t ah[4][4], bh[2][4];
            #pragma unroll
            for (int i = 0; i < 4; i++)
                ldm4(sb + (uint32_t)((wm + i * 16) + acb_row) * 80u + cb, ah[i]);
            #pragma unroll
            for (int nb = 0; nb < 2; nb++)
                ldm4(sb + 10240u + (uint32_t)((wn + nb * 16) + acb_row) * 80u + cb, bh[nb]);

            #pragma unroll
            for (int i = 0; i < 4; i++)
                #pragma unroll
                for (int nb = 0; nb < 2; nb++) {
                    mma16816(d[i][2*nb],     ah[i], bh[nb][0], bh[nb][2]);
                    mma16816(d[i][2*nb + 1], ah[i], bh[nb][1], bh[nb][3]);
                }
        }
        CPA_WAIT0();
        __syncthreads();
    }

    const int er = bm + wm + (lane >> 2);
    const int ec = bn + wn + (lane & 3) * 2;
    #pragma unroll
    for (int i = 0; i < 4; i++) {
        const int r1 = er + i * 16;
        #pragma unroll
        for (int jj = 0; jj < 4; jj++) {
            const int c = ec + jj * 8;
            size_t o0 = (size_t)r1 * GK + c;
            size_t o1 = (size_t)(r1 + 8) * GK + c;
            if (OH) {
                *(uint32_t*)(OH + o0) = pack_h2(d[i][jj][0], d[i][jj][1]);
                *(uint32_t*)(OH + o1) = pack_h2(d[i][jj][2], d[i][jj][3]);
            } else {
                float2 v0 = make_float2(d[i][jj][0], d[i][jj][1]);
                float2 v1 = make_float2(d[i][jj][2], d[i][jj][3]);
                if (resid) {
                    float2 q0 = *(const float2*)(resid + o0);
                    float2 q1 = *(const float2*)(resid + o1);
                    v0.x += q0.x; v0.y += q0.y;
                    v1.x += q1.x; v1.y += q1.y;
                }
                *(float2*)(C + o0) = v0;
                *(float2*)(C + o1) = v1;
            }
        }
    }
}

// ---------------------------------------------------------------------------
// fp32 -> fp16; grid.z selects source (q,k,v) -> plane z
// ---------------------------------------------------------------------------
__global__ __launch_bounds__(256) void conv_act_all(
    const float* __restrict__ X0, const float* __restrict__ X1,
    const float* __restrict__ X2, __half* __restrict__ H)
{
    const int z = blockIdx.z;
    const float* X = (z == 0) ? X0 : (z == 1) ? X1 : X2;
    size_t i = (size_t)blockIdx.x * 256 + threadIdx.x;
    float4 v = ((const float4*)X)[i];
    __half h[4];
    h[0] = __float2half_rn(v.x);
    h[1] = __float2half_rn(v.y);
    h[2] = __float2half_rn(v.z);
    h[3] = __float2half_rn(v.w);
    uint64_t hp;
    memcpy(&hp, h, 8);
    ((uint64_t*)H)[(size_t)z * (PSZ / 4) + i] = hp;
}

// ---------------------------------------------------------------------------
// W [K][N] fp32 -> W^T fp16 [N][K]; grid.z selects (wq,wk,wv,wo)
// ---------------------------------------------------------------------------
__global__ __launch_bounds__(256) void conv_wt_all(
    const float* __restrict__ W0, const float* __restrict__ W1,
    const float* __restrict__ W2, const float* __restrict__ W3,
    __half* __restrict__ TH)
{
    __shared__ float t[32][33];
    const int z = blockIdx.z;
    const float* W = (z == 0) ? W0 : (z == 1) ? W1 : (z == 2) ? W2 : W3;
    const size_t zw = (size_t)z * WSZ;
    const int bxn = blockIdx.x * 32;
    const int byk = blockIdx.y * 32;
    const int tx = threadIdx.x & 31;
    const int ty4 = (threadIdx.x >> 5) * 4;

    #pragma unroll
    for (int j = 0; j < 4; j++)
        t[ty4 + j][tx] = W[(size_t)(byk + ty4 + j) * Dd + bxn + tx];
    __syncthreads();

    #pragma unroll
    for (int j = 0; j < 4; j++)
        TH[zw + (size_t)(bxn + ty4 + j) * Dd + byk + tx] =
            __float2half_rn(t[tx][ty4 + j]);
}

// ---------------------------------------------------------------------------
// fp16 HMMA flash attention (causal), single-product S and O.  [R13 frozen,
// plus heavy-first CTA ordering: bx reversed so long-history tiles run in
// wave 1, shrinking the load-imbalance tail.]
// ---------------------------------------------------------------------------
#define AT_ROWB    144
#define AT_TILE_B  (64 * AT_ROWB)          // 9216
#define AT_KVSTG_B (2 * AT_TILE_B)         // 18432: Kh + Vh
#define AT_Q_B     18432
#define ATTN2_SMEM (AT_Q_B + 2 * AT_KVSTG_B)   // 55296
#define CS 0.18033688011112042f            // log2(e)/8

__global__ __launch_bounds__(256, 2) void attn_tc(
    const __half* __restrict__ Qh,
    const __half* __restrict__ Kh, const __half* __restrict__ Vh,
    __half* __restrict__ Oh)
{
    extern __shared__ char smc[];
    const int tid = threadIdx.x;
    const int lane = tid & 31;
    const int w = tid >> 5;
    const int bx = (int)gridDim.x - 1 - (int)blockIdx.x;   // heavy first
    const int h = blockIdx.y, b = blockIdx.z;
    const int q0 = bx * 128;
    const uint32_t sb = smem_u32(smc);
    const uint32_t kvb = sb + AT_Q_B;
    const size_t headoff = (size_t)b * Ss * Dd + (size_t)h * HDd;

    // ---- Q tile -> persistent SMEM
    {
        const __half* gq = Qh + headoff + (size_t)q0 * Dd;
        #pragma unroll
        for (int it = 0; it < 4; it++) {
            int f = tid + it * 256;
            int r = f >> 3, ch = f & 7;
            uint32_t so = sb + (uint32_t)(r * AT_ROWB + ch * 16);
            cpa16(so, gq + (size_t)r * Dd + ch * 8);
        }
        CPA_COMMIT();
        CPA_WAIT0();
    }
    __syncthreads();

    const uint32_t qlb = sb + (uint32_t)((16 * w + (lane & 15)) * AT_ROWB
                                         + (lane >> 4) * 16);

    float oacc[8][4];
    #pragma unroll
    for (int i = 0; i < 8; i++)
        #pragma unroll
        for (int e = 0; e < 4; e++) oacc[i][e] = 0.f;
    float m0 = -1e30f, m1 = -1e30f, l0 = 0.f, l1 = 0.f;
    const int r0g = q0 + 16 * w + (lane >> 2);
    const int r1g = r0g + 8;

    const int nkt = 2 * bx + 2;
    const __half *gkh = Kh + headoff, *gvh = Vh + headoff;

    // prologue: KV tile 0 -> stage 0
    #pragma unroll
    for (int it = 0; it < 2; it++) {
        int f = tid + it * 256;
        int r = f >> 3, ch = f & 7;
        uint32_t so = kvb + (uint32_t)(r * AT_ROWB + ch * 16);
        size_t go = (size_t)r * Dd + ch * 8;
        cpa16(so,             gkh + go);
        cpa16(so + AT_TILE_B, gvh + go);
    }
    CPA_COMMIT();

    for (int kt = 0; kt < nkt; kt++) {
        __syncthreads();
        if (kt + 1 < nkt) {
            const uint32_t st2 = kvb + (uint32_t)(((kt + 1) & 1) * AT_KVSTG_B);
            const size_t kb = (size_t)(kt + 1) * 64 * Dd;
            #pragma unroll
            for (int it = 0; it < 2; it++) {
                int f = tid + it * 256;
                int r = f >> 3, ch = f & 7;
                uint32_t so = st2 + (uint32_t)(r * AT_ROWB + ch * 16);
                size_t go = kb + (size_t)r * Dd + ch * 8;
                cpa16(so,             gkh + go);
                cpa16(so + AT_TILE_B, gvh + go);
            }
            CPA_COMMIT();
            CPA_WAIT1();
        } else {
            CPA_WAIT0();
        }
        __syncthreads();

        const int k0 = kt * 64;
        const bool active = (k0 <= q0 + 16 * w + 15);   // warp-uniform
        if (active) {
            const uint32_t stg = kvb + (uint32_t)((kt & 1) * AT_KVSTG_B);
            float sacc[8][4];
            #pragma unroll
            for (int i = 0; i < 8; i++)
                #pragma unroll
                for (int e = 0; e < 4; e++) sacc[i][e] = 0.f;

            const uint32_t lb = stg + (uint32_t)((lane & 15) * AT_ROWB
                                                 + (lane >> 4) * 16);
            #pragma unroll
            for (int c = 0; c < 4; c++) {
                uint32_t qh4[4];
                ldm4(qlb + (uint32_t)(c * 32), qh4);
                #pragma unroll
                for (int g = 0; g < 4; g++) {
                    uint32_t kh4[4];
                    ldm4(lb + (uint32_t)(g * 16 * AT_ROWB + c * 32), kh4);
                    mma16816(sacc[2*g],   qh4, kh4[0], kh4[2]);
                    mma16816(sacc[2*g+1], qh4, kh4[1], kh4[3]);
                }
            }

            if (k0 + 63 > q0 + 16 * w) {
                #pragma unroll
                for (int nb = 0; nb < 8; nb++) {
                    int col = k0 + nb * 8 + (lane & 3) * 2;
                    if (col     > r0g) sacc[nb][0] = -1e30f;
                    if (col + 1 > r0g) sacc[nb][1] = -1e30f;
                    if (col     > r1g) sacc[nb][2] = -1e30f;
                    if (col + 1 > r1g) sacc[nb][3] = -1e30f;
                }
            }

            float mx0 = -1e30f, mx1 = -1e30f;
            #pragma unroll
            for (int nb = 0; nb < 8; nb++) {
                mx0 = fmaxf(mx0, fmaxf(sacc[nb][0], sacc[nb][1]));
                mx1 = fmaxf(mx1, fmaxf(sacc[nb][2], sacc[nb][3]));
            }
            mx0 = fmaxf(mx0, __shfl_xor_sync(0xffffffffu, mx0, 1));
            mx0 = fmaxf(mx0, __shfl_xor_sync(0xffffffffu, mx0, 2));
            mx1 = fmaxf(mx1, __shfl_xor_sync(0xffffffffu, mx1, 1));
            mx1 = fmaxf(mx1, __shfl_xor_sync(0xffffffffu, mx1, 2));
            const float nm0 = fmaxf(m0, mx0), nm1 = fmaxf(m1, mx1);
            const float a0 = exp2f((m0 - nm0) * CS);
            const float a1 = exp2f((m1 - nm1) * CS);
            m0 = nm0; m1 = nm1;
            const float c0 = nm0 * CS, c1 = nm1 * CS;
            float s0 = 0.f, s1 = 0.f;
            #pragma unroll
            for (int nb = 0; nb < 8; nb++) {
                float p0 = exp2f(fmaf(sacc[nb][0], CS, -c0));
                float p1 = exp2f(fmaf(sacc[nb][1], CS, -c0));
                float p2 = exp2f(fmaf(sacc[nb][2], CS, -c1));
                float p3 = exp2f(fmaf(sacc[nb][3], CS, -c1));
                sacc[nb][0] = p0; sacc[nb][1] = p1;
                sacc[nb][2] = p2; sacc[nb][3] = p3;
                s0 += p0 + p1;
                s1 += p2 + p3;
            }
            s0 += __shfl_xor_sync(0xffffffffu, s0, 1);
            s0 += __shfl_xor_sync(0xffffffffu, s0, 2);
            s1 += __shfl_xor_sync(0xffffffffu, s1, 1);
            s1 += __shfl_xor_sync(0xffffffffu, s1, 2);
            l0 = l0 * a0 + s0;
            l1 = l1 * a1 + s1;
            #pragma unroll
            for (int i = 0; i < 8; i++) {
                oacc[i][0] *= a0; oacc[i][1] *= a0;
                oacc[i][2] *= a1; oacc[i][3] *= a1;
            }

            // O += Ph · Vh
            #pragma unroll
            for (int j = 0; j < 4; j++) {
                uint32_t pa[4];
                pa[0] = pack_h2(sacc[2*j][0],   sacc[2*j][1]);
                pa[1] = pack_h2(sacc[2*j][2],   sacc[2*j][3]);
                pa[2] = pack_h2(sacc[2*j+1][0], sacc[2*j+1][1]);
                pa[3] = pack_h2(sacc[2*j+1][2], sacc[2*j+1][3]);
                const uint32_t vb = stg + AT_TILE_B
                    + (uint32_t)((16 * j + (lane & 15)) * AT_ROWB + (lane >> 4) * 16);
                #pragma unroll
                for (int dp = 0; dp < 4; dp++) {
                    uint32_t vh4[4];
                    ldm4t(vb + (uint32_t)(dp * 32), vh4);
                    mma16816(oacc[2*dp],   pa, vh4[0], vh4[1]);
                    mma16816(oacc[2*dp+1], pa, vh4[2], vh4[3]);
                }
            }
        }
    }

    const float i0 = 1.f / l0, i1 = 1.f / l1;
    const size_t ro0 = (size_t)b * Ss * Dd + (size_t)r0g * Dd + (size_t)h * HDd;
    const size_t ro1 = ro0 + 8 * Dd;
    #pragma unroll
    for (int nb = 0; nb < 8; nb++) {
        const int dcol = nb * 8 + (lane & 3) * 2;
        *(uint32_t*)(Oh + ro0 + dcol) = pack_h2(oacc[nb][0] * i0, oacc[nb][1] * i0);
        *(uint32_t*)(Oh + ro1 + dcol) = pack_h2(oacc[nb][2] * i1, oacc[nb][3] * i1);
    }
}

// ---------------------------------------------------------------------------
// LayerNorm over last dim (1024)
// ---------------------------------------------------------------------------
__global__ __launch_bounds__(256) void ln_kernel(
    const float* __restrict__ X, const float* __restrict__ gamma,
    const float* __restrict__ beta, float* __restrict__ Y)
{
    const int row = blockIdx.x;
    const int t = threadIdx.x;
    const float4 v = ((const float4*)(X + (size_t)row * Dd))[t];

    float s  = v.x + v.y + v.z + v.w;
    float ss = v.x * v.x + v.y * v.y + v.z * v.z + v.w * v.w;
    #pragma unroll
    for (int o = 16; o > 0; o >>= 1) {
        s  += __shfl_xor_sync(0xffffffffu, s,  o);
        ss += __shfl_xor_sync(0xffffffffu, ss, o);
    }
    __shared__ float sh[8][2];
    if ((t & 31) == 0) { sh[t >> 5][0] = s; sh[t >> 5][1] = ss; }
    __syncthreads();
    float ts = 0.f, tss = 0.f;
    #pragma unroll
    for (int i = 0; i < 8; i++) { ts += sh[i][0]; tss += sh[i][1]; }

    const float mu  = ts * (1.0f / Dd);
    const float var = tss * (1.0f / Dd) - mu * mu;
    const float inv = rsqrtf(var + LN_EPS);

    const float4 gg = ((const float4*)gamma)[t];
    const float4 bb = ((const float4*)beta)[t];
    float4 y;
    y.x = (v.x - mu) * inv * gg.x + bb.x;
    y.y = (v.y - mu) * inv * gg.y + bb.y;
    y.z = (v.z - mu) * inv * gg.z + bb.z;
    y.w = (v.w - mu) * inv * gg.w + bb.w;
    ((float4*)(Y + (size_t)row * Dd))[t] = y;
}

// ---------------------------------------------------------------------------
// Launch. Inputs: q, k, v, wq, wk, wv, wo, gamma, beta, mask (causal; unused).
// ---------------------------------------------------------------------------
extern "C" void kernel_launch(void* const* d_in, const int* in_sizes, int n_in,
                              void* d_out, int out_size)
{
    const float* q     = (const float*)d_in[0];
    const float* k     = (const float*)d_in[1];
    const float* v     = (const float*)d_in[2];
    const float* wq    = (const float*)d_in[3];
    const float* wk    = (const float*)d_in[4];
    const float* wv    = (const float*)d_in[5];
    const float* wo    = (const float*)d_in[6];
    const float* gamma = (const float*)d_in[7];
    const float* beta  = (const float*)d_in[8];
    float* out = (float*)d_out;

    float* gtmp;
    __half *gxh, *gwth, *gph, *goh;
    cudaGetSymbolAddress((void**)&gtmp, g_tmp);
    cudaGetSymbolAddress((void**)&gxh,  g_xh);
    cudaGetSymbolAddress((void**)&gwth, g_wth);
    cudaGetSymbolAddress((void**)&gph,  g_ph);
    cudaGetSymbolAddress((void**)&goh,  g_oh);

    cudaFuncSetAttribute(gemm_tc,
                         cudaFuncAttributeMaxDynamicSharedMemorySize, GEMM_SMEM);
    cudaFuncSetAttribute(attn_tc,
                         cudaFuncAttributeMaxDynamicSharedMemorySize, ATTN2_SMEM);

    const dim3 blk256(256);
    const dim3 ggemm(Dd / 128, MS / 128);     // (8, 32)

    // conversions up front (2 launches)
    conv_wt_all<<<dim3(Dd / 32, Dd / 32, 4), blk256>>>(wq, wk, wv, wo, gwth);
    conv_act_all<<<dim3(MS * Dd / 4 / 256, 1, 3), blk256>>>(q, k, v, gxh);

    // Q/K/V projections (single-product, fp16 outputs) — R13 proven form
    gemm_tc<<<ggemm, blk256, GEMM_SMEM>>>(
        gxh,           gwth,           nullptr, nullptr, gph);
    gemm_tc<<<ggemm, blk256, GEMM_SMEM>>>(
        gxh + PSZ,     gwth + WSZ,     nullptr, nullptr, gph + PSZ);
    gemm_tc<<<ggemm, blk256, GEMM_SMEM>>>(
        gxh + 2 * PSZ, gwth + 2 * WSZ, nullptr, nullptr, gph + 2 * PSZ);

    // flash attention: single-product S and O, heavy CTAs first
    attn_tc<<<dim3(Ss / 128, Hh, Bb), blk256, ATTN2_SMEM>>>(
        gph, gph + PSZ, gph + 2 * PSZ, goh);

    // output projection + residual (fp32 out)
    gemm_tc<<<ggemm, blk256, GEMM_SMEM>>>(
        goh, gwth + 3 * WSZ, q, gtmp, nullptr);

    // LayerNorm
    ln_kernel<<<MS, blk256>>>(gtmp, gamma, beta, out);
}